// round 3
// baseline (speedup 1.0000x reference)
#include <cuda_runtime.h>

typedef unsigned long long ull;

#define TN      128
#define THREADS 512
#define CC      128
#define KD      32

// float4-granular smem layout (pitch 33 float4 = 132 floats per row)
#define XS_F4   0
#define XS_N4   (TN * 33)                 // 4224
#define W1T_F4  (XS_F4 + XS_N4)           // W1t [128c][33], overlaid by hs after stage 1
#define W1T_N4  (CC * 33)                 // 4224
#define W2T_F4  (W1T_F4 + W1T_N4)         // W2t [32k][33]
#define W2T_N4  (KD * 33)                 // 1056
#define SS_F    ((W2T_F4 + W2T_N4) * 4)   // ss [128][32] floats
#define IB_I    (SS_F + TN * KD)          // 128 ints
#define SMEM_BYTES ((IB_I + TN) * 4)      // 168960 B

__device__ float g_W1t[CC * CC];          // [c][k]
__device__ float g_W2t[KD * CC];          // [k][j]

static __device__ __forceinline__ ull pk2(float lo, float hi) {
    ull r; asm("mov.b64 %0,{%1,%2};" : "=l"(r) : "f"(lo), "f"(hi)); return r;
}
static __device__ __forceinline__ float2 upk2(ull v) {
    float2 f; asm("mov.b64 {%0,%1},%2;" : "=f"(f.x), "=f"(f.y) : "l"(v)); return f;
}
static __device__ __forceinline__ ull ffma2_(ull a, ull b, ull c) {
    ull d; asm("fma.rn.f32x2 %0,%1,%2,%3;" : "=l"(d) : "l"(a), "l"(b), "l"(c)); return d;
}

__global__ void hp_zero_kernel(float4* __restrict__ o, int n4) {
    int i = blockIdx.x * blockDim.x + threadIdx.x;
    float4 z = make_float4(0.f, 0.f, 0.f, 0.f);
    for (; i < n4; i += gridDim.x * blockDim.x) o[i] = z;
}

// dst[C][R] = src[R][C]^T   (32x32 tiles, 32x8 threads)
__global__ void hp_tr_kernel(float* __restrict__ dst, const float* __restrict__ src,
                             int R, int C) {
    __shared__ float t[32][33];
    int x = blockIdx.x * 32 + threadIdx.x;
    int y0 = blockIdx.y * 32 + threadIdx.y;
    #pragma unroll
    for (int i = 0; i < 32; i += 8)
        if (y0 + i < R && x < C) t[threadIdx.y + i][threadIdx.x] = src[(y0 + i) * C + x];
    __syncthreads();
    int xo = blockIdx.y * 32 + threadIdx.x;
    int yo0 = blockIdx.x * 32 + threadIdx.y;
    #pragma unroll
    for (int i = 0; i < 32; i += 8)
        if (yo0 + i < C && xo < R) dst[(yo0 + i) * R + xo] = t[threadIdx.x][threadIdx.y + i];
}

__global__ void hp_tr1_kernel(const float* __restrict__ W1) {
    hp_tr_kernel; // silence unused warnings trick not needed; separate body below
}

__global__ __launch_bounds__(THREADS, 1)
void hp_main_kernel(const float* __restrict__ x, const int* __restrict__ batch,
                    const float* __restrict__ b1, const float* __restrict__ b2,
                    float* __restrict__ out, float* __restrict__ s_out, int N)
{
    extern __shared__ __align__(16) char smem[];
    float4* xs4  = (float4*)smem + XS_F4;
    float4* w1t4 = (float4*)smem + W1T_F4;
    float*  hs   = (float*)((float4*)smem + W1T_F4);   // overlays W1t after stage 1
    float4* hs4  = (float4*)hs;
    float4* w2t4 = (float4*)smem + W2T_F4;
    float*  ss   = (float*)smem + SS_F;
    int*    ib   = (int*)smem + IB_I;

    const int tid  = threadIdx.x;
    const int lane = tid & 31;
    const int n0   = blockIdx.x * TN;
    const int nvalid = min(TN, N - n0);

    // ================= staging (all coalesced / conflict-free) =================
    if (tid < TN) ib[tid] = (n0 + tid < N) ? batch[n0 + tid] : -1;

    {
        const float4* xg = (const float4*)x;
        #pragma unroll
        for (int it = 0; it < (TN * 32) / THREADS; ++it) {
            int idx = it * THREADS + tid;
            int n = idx >> 5, g = idx & 31;
            float4 v = make_float4(0.f, 0.f, 0.f, 0.f);
            if (n < nvalid) v = xg[(size_t)(n0 + n) * 32 + g];
            xs4[n * 33 + g] = v;
        }
        const float4* wg = (const float4*)g_W1t;
        #pragma unroll
        for (int it = 0; it < (CC * 32) / THREADS; ++it) {
            int idx = it * THREADS + tid;
            int c = idx >> 5, g = idx & 31;
            w1t4[c * 33 + g] = wg[c * 32 + g];
        }
        const float4* w2g = (const float4*)g_W2t;
        #pragma unroll
        for (int it = 0; it < (KD * 32) / THREADS; ++it) {
            int idx = it * THREADS + tid;
            int k = idx >> 5, g = idx & 31;
            w2t4[k * 33 + g] = w2g[k * 32 + g];
        }
    }
    __syncthreads();

    // ========== stage 1: H = relu(X @ W1 + b1). thread: 4 nodes x 8 cols ==========
    // cg = tid&15 -> cols c = i*16+cg ; ng = tid>>4 -> nodes n = ng*4+r
    {
        const int cg = tid & 15;
        const int ng = tid >> 4;
        ull acc[4][8];
        #pragma unroll
        for (int r = 0; r < 4; ++r)
            #pragma unroll
            for (int i = 0; i < 8; ++i) acc[r][i] = 0ull;

        #pragma unroll 2
        for (int k4 = 0; k4 < 32; ++k4) {
            float4 xa[4];
            ull xp[4][2];
            #pragma unroll
            for (int r = 0; r < 4; ++r) {
                xa[r] = xs4[(ng * 4 + r) * 33 + k4];
                xp[r][0] = pk2(xa[r].x, xa[r].y);
                xp[r][1] = pk2(xa[r].z, xa[r].w);
            }
            #pragma unroll
            for (int i = 0; i < 8; ++i) {
                float4 wv = w1t4[(i * 16 + cg) * 33 + k4];
                ull w0 = pk2(wv.x, wv.y);
                ull w1p = pk2(wv.z, wv.w);
                #pragma unroll
                for (int r = 0; r < 4; ++r) {
                    acc[r][i] = ffma2_(xp[r][0], w0, acc[r][i]);
                    acc[r][i] = ffma2_(xp[r][1], w1p, acc[r][i]);
                }
            }
        }
        __syncthreads();   // everyone done reading W1t before hs overlays it

        float bv[8];
        #pragma unroll
        for (int i = 0; i < 8; ++i) bv[i] = b1[i * 16 + cg];
        #pragma unroll
        for (int r = 0; r < 4; ++r) {
            int n = ng * 4 + r;
            #pragma unroll
            for (int i = 0; i < 8; ++i) {
                float2 f = upk2(acc[r][i]);
                hs[n * 132 + i * 16 + cg] = fmaxf(f.x + f.y + bv[i], 0.f);
            }
        }
    }
    __syncthreads();

    // ========== stage 2: logits = H @ W2 + b2. thread: 2 nodes x 4 k ==========
    // kg = tid&7 -> k = i*8+kg ; nq = tid>>3 -> nodes nq*2, nq*2+1
    {
        const int kg = tid & 7;
        const int nq = tid >> 3;
        ull acc[2][4];
        #pragma unroll
        for (int a = 0; a < 2; ++a)
            #pragma unroll
            for (int i = 0; i < 4; ++i) acc[a][i] = 0ull;

        #pragma unroll 2
        for (int j4 = 0; j4 < 32; ++j4) {
            float4 h0 = hs4[(nq * 2) * 33 + j4];
            float4 h1 = hs4[(nq * 2 + 1) * 33 + j4];
            ull h0a = pk2(h0.x, h0.y), h0b = pk2(h0.z, h0.w);
            ull h1a = pk2(h1.x, h1.y), h1b = pk2(h1.z, h1.w);
            #pragma unroll
            for (int i = 0; i < 4; ++i) {
                float4 wv = w2t4[(i * 8 + kg) * 33 + j4];
                ull w0 = pk2(wv.x, wv.y);
                ull w1p = pk2(wv.z, wv.w);
                acc[0][i] = ffma2_(h0a, w0, acc[0][i]);
                acc[0][i] = ffma2_(h0b, w1p, acc[0][i]);
                acc[1][i] = ffma2_(h1a, w0, acc[1][i]);
                acc[1][i] = ffma2_(h1b, w1p, acc[1][i]);
            }
        }
        #pragma unroll
        for (int a = 0; a < 2; ++a) {
            int n = nq * 2 + a;
            #pragma unroll
            for (int i = 0; i < 4; ++i) {
                float2 f = upk2(acc[a][i]);
                ss[n * KD + i * 8 + kg] = f.x + f.y + b2[i * 8 + kg];
            }
        }
    }
    __syncthreads();

    // ========== stage 3: softmax per node (warp per node, lane = k) ==========
    {
        const int w = tid >> 5;
        #pragma unroll
        for (int i = 0; i < 8; ++i) {
            int n = w * 8 + i;
            float v = ss[n * KD + lane];
            float m = v;
            #pragma unroll
            for (int o = 16; o > 0; o >>= 1) m = fmaxf(m, __shfl_xor_sync(0xffffffffu, m, o));
            float e = __expf(v - m);
            float sum = e;
            #pragma unroll
            for (int o = 16; o > 0; o >>= 1) sum += __shfl_xor_sync(0xffffffffu, sum, o);
            float sv = e / sum;
            ss[n * KD + lane] = sv;
            if (n0 + n < N) s_out[(size_t)(n0 + n) * KD + lane] = sv;
        }
    }
    __syncthreads();

    // ========== stage 4: out[b][k][c] += sum_n s[n][k]*x[n][c] ==========
    // warp w: kw=w&3 (k base kw*8), cw=w>>2 (c base cw*32)
    // lane: cl=lane&7 -> c = cw*32+cl*4 ; kq=lane>>3 -> k = kw*8+kq*2
    {
        const int w  = tid >> 5;
        const int kw = w & 3;
        const int cw = w >> 2;
        const int cl = lane & 7;
        const int kq = lane >> 3;
        const int k0 = kw * 8 + kq * 2;
        const int c0 = cw * 32 + cl * 4;

        int bmin = ib[0];
        int bmax = ib[nvalid - 1];
        for (int b = bmin; b <= bmax; ++b) {
            ull acc[2][2];
            acc[0][0] = acc[0][1] = acc[1][0] = acc[1][1] = 0ull;
            for (int n = 0; n < TN; ++n) {
                if (ib[n] != b) continue;   // uniform across block
                ull sv = *(const ull*)&ss[n * KD + k0];
                float2 sf = upk2(sv);
                ull d0 = pk2(sf.x, sf.x);
                ull d1 = pk2(sf.y, sf.y);
                float4 xv = xs4[n * 33 + cw * 8 + cl];
                ull xp0 = pk2(xv.x, xv.y);
                ull xp1 = pk2(xv.z, xv.w);
                acc[0][0] = ffma2_(d0, xp0, acc[0][0]);
                acc[0][1] = ffma2_(d0, xp1, acc[0][1]);
                acc[1][0] = ffma2_(d1, xp0, acc[1][0]);
                acc[1][1] = ffma2_(d1, xp1, acc[1][1]);
            }
            float* ob = out + (size_t)b * (KD * CC);
            #pragma unroll
            for (int a = 0; a < 2; ++a)
                #pragma unroll
                for (int p = 0; p < 2; ++p) {
                    float2 f = upk2(acc[a][p]);
                    atomicAdd(&ob[(k0 + a) * CC + c0 + p * 2 + 0], f.x);
                    atomicAdd(&ob[(k0 + a) * CC + c0 + p * 2 + 1], f.y);
                }
        }
    }
}

extern "C" void kernel_launch(void* const* d_in, const int* in_sizes, int n_in,
                              void* d_out, int out_size)
{
    const float* x     = (const float*)d_in[0];
    const int*   batch = (const int*)d_in[1];
    const float* W1    = (const float*)d_in[2];
    const float* b1    = (const float*)d_in[3];
    const float* W2    = (const float*)d_in[4];
    const float* b2    = (const float*)d_in[5];

    const int N = in_sizes[1];
    float* out = (float*)d_out;
    size_t out_elems = (size_t)out_size - (size_t)N * KD;   // B*K*C
    float* s_out = out + out_elems;

    // zero the pooled-output region (poisoned by harness)
    {
        int n4 = (int)(out_elems / 4);
        int blocks = (n4 + 255) / 256;
        if (blocks > 512) blocks = 512;
        hp_zero_kernel<<<blocks, 256>>>((float4*)out, n4);
    }

    // global weight transposes: g_W1t[c][k] = W1[k][c], g_W2t[k][j] = W2[j][k]
    {
        float* w1t_ptr = nullptr;
        float* w2t_ptr = nullptr;
        cudaGetSymbolAddress((void**)&w1t_ptr, g_W1t);
        cudaGetSymbolAddress((void**)&w2t_ptr, g_W2t);
        dim3 thr(32, 8);
        hp_tr_kernel<<<dim3(4, 4), thr>>>(w1t_ptr, W1, CC, CC);
        hp_tr_kernel<<<dim3(1, 4), thr>>>(w2t_ptr, W2, CC, KD);
    }

    cudaFuncSetAttribute(hp_main_kernel,
                         cudaFuncAttributeMaxDynamicSharedMemorySize, SMEM_BYTES);
    int nb = (N + TN - 1) / TN;
    hp_main_kernel<<<nb, THREADS, SMEM_BYTES>>>(x, batch, b1, b2, out, s_out, N);
}

// round 4
// speedup vs baseline: 1.2855x; 1.2855x over previous
#include <cuda_runtime.h>

typedef unsigned long long ull;

#define TN      64
#define THREADS 128
#define CC      128
#define KD      32

// float offsets in dynamic smem
#define XSN_F   0                      // xsn [64 n][136] node-major, lives whole kernel
#define XSN_NF  (TN * 136)             // 8704 floats
#define REG_F   XSN_NF                 // region: W1 [128][128] (16384 f) -> hs[64][136] + W2s[128][32]
#define HS_F    REG_F                  // hs at region start (after stage-1 barrier)
#define W2_F    (REG_F + TN * 136)     // 8704 + 8704 = 17408
#define SS_F    (REG_F + CC * CC)      // 8704 + 16384 = 25088 ; ss [64][32]
#define IB_I    (SS_F + TN * KD)       // 27136
#define SMEM_FLOATS (IB_I + TN)        // 27200
#define SMEM_BYTES  (SMEM_FLOATS * 4)  // 108800

static __device__ __forceinline__ ull pk2(float lo, float hi) {
    ull r; asm("mov.b64 %0,{%1,%2};" : "=l"(r) : "f"(lo), "f"(hi)); return r;
}
static __device__ __forceinline__ float2 upk2(ull v) {
    float2 f; asm("mov.b64 {%0,%1},%2;" : "=f"(f.x), "=f"(f.y) : "l"(v)); return f;
}
static __device__ __forceinline__ ull ffma2_(ull a, ull b, ull c) {
    ull d; asm("fma.rn.f32x2 %0,%1,%2,%3;" : "=l"(d) : "l"(a), "l"(b), "l"(c)); return d;
}

__global__ void hp_zero_kernel(float4* __restrict__ o, int n4) {
    int i = blockIdx.x * blockDim.x + threadIdx.x;
    float4 z = make_float4(0.f, 0.f, 0.f, 0.f);
    for (; i < n4; i += gridDim.x * blockDim.x) o[i] = z;
}

__global__ __launch_bounds__(THREADS, 2)
void hp_main_kernel(const float* __restrict__ x, const int* __restrict__ batch,
                    const float* __restrict__ W1, const float* __restrict__ b1,
                    const float* __restrict__ W2, const float* __restrict__ b2,
                    float* __restrict__ out, float* __restrict__ s_out, int N)
{
    extern __shared__ __align__(16) float smem[];
    float4* xsn4 = (float4*)(smem + XSN_F);      // pitch 34 f4
    float4* w1s4 = (float4*)(smem + REG_F);      // pitch 32 f4
    float*  hs   = smem + HS_F;                  // pitch 136 f
    float4* hs4  = (float4*)hs;                  // pitch 34 f4
    float4* w2s4 = (float4*)(smem + W2_F);       // pitch 8 f4
    float*  ss   = smem + SS_F;                  // pitch 32 f
    float4* ss4  = (float4*)ss;                  // pitch 8 f4
    int*    ib   = (int*)(smem + IB_I);

    const int tid  = threadIdx.x;
    const int lane = tid & 31;
    const int wrp  = tid >> 5;          // 0..3
    const int n0   = blockIdx.x * TN;
    const int nvalid = min(TN, N - n0);

    // ================= staging: ib, xsn (node-major, coalesced), W1 =================
    if (tid < TN) ib[tid] = (n0 + tid < N) ? batch[n0 + tid] : -1;

    {
        const float4* xg = (const float4*)x;
        #pragma unroll
        for (int it = 0; it < (TN * 32) / THREADS; ++it) {   // 16 iters
            int idx = it * THREADS + tid;
            int n = idx >> 5, g = idx & 31;
            float4 v = make_float4(0.f, 0.f, 0.f, 0.f);
            if (n < nvalid) v = xg[(size_t)(n0 + n) * 32 + g];
            xsn4[n * 34 + g] = v;
        }
        const float4* wg = (const float4*)W1;
        #pragma unroll
        for (int it = 0; it < (CC * 32) / THREADS; ++it)     // 32 iters
            w1s4[it * THREADS + tid] = wg[it * THREADS + tid];
    }
    __syncthreads();

    // ===== stage 1: H = relu(X @ W1 + b1) =====
    // tc = tid&15 -> cols {4tc..4tc+3} U {64+4tc..+3}; ty = tid>>4 -> nodes n = ty + 8r
    {
        const int tc = tid & 15;
        const int ty = tid >> 4;
        float4 b1a = ((const float4*)b1)[tc];
        float4 b1b = ((const float4*)b1)[16 + tc];
        ull acc[8][4];
        #pragma unroll
        for (int r = 0; r < 8; ++r) {
            acc[r][0] = pk2(b1a.x, b1a.y);
            acc[r][1] = pk2(b1a.z, b1a.w);
            acc[r][2] = pk2(b1b.x, b1b.y);
            acc[r][3] = pk2(b1b.z, b1b.w);
        }

        for (int k4 = 0; k4 < 32; ++k4) {
            float4 xf[8];
            #pragma unroll
            for (int r = 0; r < 8; ++r) xf[r] = xsn4[(ty + 8 * r) * 34 + k4];
            #pragma unroll
            for (int kk = 0; kk < 4; ++kk) {
                float4 wA = w1s4[(k4 * 4 + kk) * 32 + tc];
                float4 wB = w1s4[(k4 * 4 + kk) * 32 + 16 + tc];
                ull wp0 = pk2(wA.x, wA.y), wp1 = pk2(wA.z, wA.w);
                ull wp2 = pk2(wB.x, wB.y), wp3 = pk2(wB.z, wB.w);
                #pragma unroll
                for (int r = 0; r < 8; ++r) {
                    float xk = (kk == 0) ? xf[r].x : (kk == 1) ? xf[r].y
                             : (kk == 2) ? xf[r].z : xf[r].w;
                    ull xp = pk2(xk, xk);
                    acc[r][0] = ffma2_(xp, wp0, acc[r][0]);
                    acc[r][1] = ffma2_(xp, wp1, acc[r][1]);
                    acc[r][2] = ffma2_(xp, wp2, acc[r][2]);
                    acc[r][3] = ffma2_(xp, wp3, acc[r][3]);
                }
            }
        }
        __syncthreads();   // all warps done reading W1 before hs/W2 overlay it

        #pragma unroll
        for (int r = 0; r < 8; ++r) {
            int n = ty + 8 * r;
            float2 a0 = upk2(acc[r][0]), a1 = upk2(acc[r][1]);
            float2 a2 = upk2(acc[r][2]), a3 = upk2(acc[r][3]);
            *(float4*)&hs[n * 136 + tc * 4] =
                make_float4(fmaxf(a0.x, 0.f), fmaxf(a0.y, 0.f),
                            fmaxf(a1.x, 0.f), fmaxf(a1.y, 0.f));
            *(float4*)&hs[n * 136 + 64 + tc * 4] =
                make_float4(fmaxf(a2.x, 0.f), fmaxf(a2.y, 0.f),
                            fmaxf(a3.x, 0.f), fmaxf(a3.y, 0.f));
        }
    }
    {
        const float4* w2g = (const float4*)W2;
        #pragma unroll
        for (int it = 0; it < (CC * 8) / THREADS; ++it)      // 8 iters
            w2s4[it * THREADS + tid] = w2g[it * THREADS + tid];
    }
    __syncthreads();

    // ===== stage 2: logits = H @ W2 + b2 =====
    // kg = tid&7 -> k = 4kg..4kg+3 ; nq = tid>>3 -> nodes n = nq + 16a, a=0..3
    {
        const int kg = tid & 7;
        const int nq = tid >> 3;
        float4 b2v = ((const float4*)b2)[kg];
        ull acc[4][2];
        #pragma unroll
        for (int a = 0; a < 4; ++a) {
            acc[a][0] = pk2(b2v.x, b2v.y);
            acc[a][1] = pk2(b2v.z, b2v.w);
        }
        for (int j4 = 0; j4 < 32; ++j4) {
            float4 hf[4];
            #pragma unroll
            for (int a = 0; a < 4; ++a) hf[a] = hs4[(nq + 16 * a) * 34 + j4];
            #pragma unroll
            for (int jj = 0; jj < 4; ++jj) {
                float4 w = w2s4[(j4 * 4 + jj) * 8 + kg];
                ull wp0 = pk2(w.x, w.y), wp1 = pk2(w.z, w.w);
                #pragma unroll
                for (int a = 0; a < 4; ++a) {
                    float hv = (jj == 0) ? hf[a].x : (jj == 1) ? hf[a].y
                             : (jj == 2) ? hf[a].z : hf[a].w;
                    ull hp = pk2(hv, hv);
                    acc[a][0] = ffma2_(hp, wp0, acc[a][0]);
                    acc[a][1] = ffma2_(hp, wp1, acc[a][1]);
                }
            }
        }
        #pragma unroll
        for (int a = 0; a < 4; ++a) {
            int n = nq + 16 * a;
            float2 p0 = upk2(acc[a][0]), p1 = upk2(acc[a][1]);
            *(float4*)&ss[n * KD + kg * 4] = make_float4(p0.x, p0.y, p1.x, p1.y);
        }
    }
    __syncthreads();

    // ===== stage 3: softmax per node (warp per node-group, lane = k) =====
    {
        #pragma unroll
        for (int i = 0; i < 16; ++i) {
            int n = wrp * 16 + i;
            float v = ss[n * KD + lane];
            float m = v;
            #pragma unroll
            for (int o = 16; o > 0; o >>= 1) m = fmaxf(m, __shfl_xor_sync(0xffffffffu, m, o));
            float e = __expf(v - m);
            float sum = e;
            #pragma unroll
            for (int o = 16; o > 0; o >>= 1) sum += __shfl_xor_sync(0xffffffffu, sum, o);
            float sv = e / sum;
            ss[n * KD + lane] = sv;
            if (n0 + n < N) s_out[(size_t)(n0 + n) * KD + lane] = sv;
        }
    }
    __syncthreads();

    // ===== stage 4: out[b][k][c] += sum_n s[n][k] * x[n][c] =====
    // warp wrp -> c chunk [wrp*32, wrp*32+32); lane: cl=lane&7 -> c = wrp*32+cl*4,
    // kq=lane>>3 -> k = kq*8..kq*8+7
    {
        const int cl = lane & 7;
        const int kq = lane >> 3;
        const int c0 = wrp * 32 + cl * 4;
        const int k0 = kq * 8;

        int bmin = ib[0];
        int bmax = ib[nvalid - 1];
        for (int b = bmin; b <= bmax; ++b) {
            ull acc[8][2];
            #pragma unroll
            for (int kk = 0; kk < 8; ++kk) { acc[kk][0] = 0ull; acc[kk][1] = 0ull; }

            for (int n = 0; n < TN; ++n) {
                if (ib[n] != b) continue;   // uniform across block
                float4 sA = ss4[n * 8 + kq * 2];
                float4 sB = ss4[n * 8 + kq * 2 + 1];
                float4 xv = xsn4[n * 34 + wrp * 8 + cl];
                ull xp0 = pk2(xv.x, xv.y);
                ull xp1 = pk2(xv.z, xv.w);
                float sk[8] = {sA.x, sA.y, sA.z, sA.w, sB.x, sB.y, sB.z, sB.w};
                #pragma unroll
                for (int kk = 0; kk < 8; ++kk) {
                    ull sp = pk2(sk[kk], sk[kk]);
                    acc[kk][0] = ffma2_(sp, xp0, acc[kk][0]);
                    acc[kk][1] = ffma2_(sp, xp1, acc[kk][1]);
                }
            }
            float* ob = out + (size_t)b * (KD * CC);
            #pragma unroll
            for (int kk = 0; kk < 8; ++kk) {
                float2 f0 = upk2(acc[kk][0]);
                float2 f1 = upk2(acc[kk][1]);
                float* p = &ob[(k0 + kk) * CC + c0];
                atomicAdd(p + 0, f0.x);
                atomicAdd(p + 1, f0.y);
                atomicAdd(p + 2, f1.x);
                atomicAdd(p + 3, f1.y);
            }
        }
    }
}

extern "C" void kernel_launch(void* const* d_in, const int* in_sizes, int n_in,
                              void* d_out, int out_size)
{
    const float* x     = (const float*)d_in[0];
    const int*   batch = (const int*)d_in[1];
    const float* W1    = (const float*)d_in[2];
    const float* b1    = (const float*)d_in[3];
    const float* W2    = (const float*)d_in[4];
    const float* b2    = (const float*)d_in[5];

    const int N = in_sizes[1];
    float* out = (float*)d_out;
    size_t out_elems = (size_t)out_size - (size_t)N * KD;   // B*K*C
    float* s_out = out + out_elems;

    // zero the pooled-output region (poisoned by harness)
    {
        int n4 = (int)(out_elems / 4);
        int blocks = (n4 + 255) / 256;
        if (blocks > 512) blocks = 512;
        hp_zero_kernel<<<blocks, 256>>>((float4*)out, n4);
    }

    cudaFuncSetAttribute(hp_main_kernel,
                         cudaFuncAttributeMaxDynamicSharedMemorySize, SMEM_BYTES);
    int nb = (N + TN - 1) / TN;
    hp_main_kernel<<<nb, THREADS, SMEM_BYTES>>>(x, batch, W1, b1, W2, b2, out, s_out, N);
}